// round 1
// baseline (speedup 1.0000x reference)
#include <cuda_runtime.h>
#include <cuda_bf16.h>
#include <math.h>

// Problem constants
#define BATCH 4
#define SEQ   1024
#define EMB   1024
#define HEADS 16
#define HDIM  64
#define HID   1024            // HEADS*HDIM
#define WIN   128             // half-window
#define NREL  257             // 2*WIN+1
#define NRELP 384             // padded to multiple of 128 for GEMM

// ---------------- scratch (no cudaMalloc allowed) ----------------
__device__ float g_qc[(size_t)BATCH*HEADS*SEQ*HDIM];   // q + content_bias, [b][h][t][d]
__device__ float g_qr[(size_t)BATCH*HEADS*SEQ*HDIM];   // q + relative_bias
__device__ float g_k [(size_t)BATCH*HEADS*SEQ*HDIM];
__device__ float g_v [(size_t)BATCH*HEADS*SEQ*HDIM];
__device__ float g_rel[(size_t)BATCH*HEADS*SEQ*NRELP]; // REL[b,h,t,u]
__device__ float g_ao[(size_t)BATCH*SEQ*HID];          // attention output, [b][t][h*64+d]
__device__ float g_rwint[64*NRELP];                    // RwinT[d][u]

// ---------------- Rwin precompute ----------------
// RwinT[d][u] = b_rel[d] + sum_dd enc(pos=u-128, dd) * W_rel[dd][d],  u in [0,257)
__global__ void rwin_kernel(const float* __restrict__ W_rel,
                            const float* __restrict__ b_rel,
                            float* __restrict__ RwinT) {
    int gid = blockIdx.x * blockDim.x + threadIdx.x;
    if (gid >= 64 * NRELP) return;
    int u = gid % NRELP;
    int d = gid / NRELP;
    float out = 0.0f;
    if (u < NREL) {
        float pos = (float)(u - WIN);
        float s = b_rel[d];
        #pragma unroll 8
        for (int f = 0; f < 32; f++) {
            float inv = powf(10000.0f, -(2.0f * (float)f) / 64.0f);
            float a = pos * inv;
            s += sinf(a) * W_rel[f * 64 + d];
            s += cosf(a) * W_rel[(f + 32) * 64 + d];
        }
        out = s;
    }
    RwinT[d * NRELP + u] = out;
}

// ---------------- generic fp32 SGEMM, 128x128x16, 256 threads, 8x8 microtile ----
// modes: 0 rowmajor C; 1 rowmajor C + bias1[n]; 2 bhtd layout C;
//        3 bhtd layout, C = acc + bias1[n], C2 = acc + bias2[n]
__global__ void __launch_bounds__(256, 2)
sgemm_kernel(const float* __restrict__ A, int lda,
             const float* __restrict__ B, int ldb,
             float* __restrict__ C, float* __restrict__ C2,
             const float* __restrict__ bias1,
             const float* __restrict__ bias2,
             int M, int N, int K, int mode) {
    __shared__ float As[16][132];
    __shared__ float Bs[16][132];

    int tid = threadIdx.x;
    int tx = tid & 15, ty = tid >> 4;
    int m0 = blockIdx.y * 128, n0 = blockIdx.x * 128;
    int arow = tid >> 2;            // 0..63
    int acol = (tid & 3) << 2;      // 0,4,8,12
    int brow = tid >> 5;            // 0..7
    int bcol = (tid & 31) << 2;     // 0..124

    float acc[8][8];
    #pragma unroll
    for (int i = 0; i < 8; i++)
        #pragma unroll
        for (int j = 0; j < 8; j++) acc[i][j] = 0.0f;

    for (int k0 = 0; k0 < K; k0 += 16) {
        #pragma unroll
        for (int r = 0; r < 128; r += 64) {
            float4 v = *(const float4*)(A + (size_t)(m0 + arow + r) * lda + k0 + acol);
            As[acol + 0][arow + r] = v.x;
            As[acol + 1][arow + r] = v.y;
            As[acol + 2][arow + r] = v.z;
            As[acol + 3][arow + r] = v.w;
        }
        #pragma unroll
        for (int r = 0; r < 16; r += 8) {
            float4 v = *(const float4*)(B + (size_t)(k0 + brow + r) * ldb + n0 + bcol);
            *(float4*)&Bs[brow + r][bcol] = v;
        }
        __syncthreads();
        #pragma unroll
        for (int kk = 0; kk < 16; kk++) {
            float4 a0 = *(float4*)&As[kk][ty * 8];
            float4 a1 = *(float4*)&As[kk][ty * 8 + 4];
            float4 b0 = *(float4*)&Bs[kk][tx * 8];
            float4 b1 = *(float4*)&Bs[kk][tx * 8 + 4];
            float av[8] = {a0.x, a0.y, a0.z, a0.w, a1.x, a1.y, a1.z, a1.w};
            float bv[8] = {b0.x, b0.y, b0.z, b0.w, b1.x, b1.y, b1.z, b1.w};
            #pragma unroll
            for (int i = 0; i < 8; i++)
                #pragma unroll
                for (int j = 0; j < 8; j++) acc[i][j] += av[i] * bv[j];
        }
        __syncthreads();
    }

    if (mode <= 1) {
        #pragma unroll
        for (int i = 0; i < 8; i++) {
            int m = m0 + ty * 8 + i;
            size_t off = (size_t)m * N + n0 + tx * 8;
            #pragma unroll
            for (int j = 0; j < 8; j++) {
                float v = acc[i][j];
                if (mode == 1) v += bias1[n0 + tx * 8 + j];
                C[off + j] = v;
            }
        }
    } else {
        #pragma unroll
        for (int i = 0; i < 8; i++) {
            int m = m0 + ty * 8 + i;
            int bb = m >> 10, t = m & 1023;
            #pragma unroll
            for (int j = 0; j < 8; j++) {
                int n = n0 + tx * 8 + j;
                int hh = n >> 6, dd = n & 63;
                size_t idx = ((size_t)(bb * HEADS + hh) << 16) + ((size_t)t << 6) + dd;
                if (mode == 2) {
                    C[idx] = acc[i][j];
                } else {
                    C[idx]  = acc[i][j] + bias1[n];
                    C2[idx] = acc[i][j] + bias2[n];
                }
            }
        }
    }
}

// ---------------- windowed attention ----------------
// block: (tile of 64 queries, h, b). 256 threads.
#define TQ   64
#define SPAN 320        // TQ + 2*WIN
#define SP   328        // padded Ssm row
#define DP   68         // padded 64-wide rows
#define ATTN_SMEM_FLOATS (2 * 64 * DP + 64 * SP)

__global__ void __launch_bounds__(256, 1)
attn_kernel(const float* __restrict__ QC,
            const float* __restrict__ KT,
            const float* __restrict__ VT,
            const float* __restrict__ REL,
            float* __restrict__ AO) {
    extern __shared__ float sm[];
    float* Qst = sm;                  // [64][DP]  Qst[d][t]
    float* Kst = sm + 64 * DP;        // [64][DP]  Kst[d][j]; reused as Vs[j][d]
    float* Ssm = sm + 2 * 64 * DP;    // [64][SP]

    int tid = threadIdx.x;
    int tx = tid & 15, ty = tid >> 4;
    int t0 = blockIdx.x * TQ;
    int h = blockIdx.y, b = blockIdx.z;
    size_t bh = (size_t)(b * HEADS + h);
    const float* qb = QC + (bh << 16) + (size_t)t0 * HDIM;
    const float* kb = KT + (bh << 16);
    const float* vb = VT + (bh << 16);
    const float* relb = REL + (bh * SEQ + t0) * NRELP;

    // load Q tile transposed: Qst[d][t]
    #pragma unroll
    for (int l = 0; l < 4; l++) {
        int fidx = tid + l * 256;          // 1024 float4s
        int t = fidx >> 4;
        int d = (fidx & 15) << 2;
        float4 v = *(const float4*)(qb + t * HDIM + d);
        Qst[(d + 0) * DP + t] = v.x;
        Qst[(d + 1) * DP + t] = v.y;
        Qst[(d + 2) * DP + t] = v.z;
        Qst[(d + 3) * DP + t] = v.w;
    }

    // ---- scores S = Qc @ K^T  (+ REL gather, scale, mask) ----
    for (int c = 0; c < 5; c++) {
        int j0 = t0 - WIN + c * 64;
        __syncthreads();   // Kst free (also orders Q load before first compute)
        #pragma unroll
        for (int l = 0; l < 4; l++) {
            int fidx = tid + l * 256;
            int jl = fidx >> 4;
            int d = (fidx & 15) << 2;
            int jg = j0 + jl;
            float4 v = make_float4(0.f, 0.f, 0.f, 0.f);
            if (jg >= 0 && jg < SEQ) v = *(const float4*)(kb + (size_t)jg * HDIM + d);
            Kst[(d + 0) * DP + jl] = v.x;
            Kst[(d + 1) * DP + jl] = v.y;
            Kst[(d + 2) * DP + jl] = v.z;
            Kst[(d + 3) * DP + jl] = v.w;
        }
        __syncthreads();

        float acc[4][4];
        #pragma unroll
        for (int i = 0; i < 4; i++)
            #pragma unroll
            for (int j = 0; j < 4; j++) acc[i][j] = 0.0f;

        #pragma unroll 8
        for (int kk = 0; kk < 64; kk++) {
            float4 a = *(float4*)&Qst[kk * DP + ty * 4];
            float4 bb = *(float4*)&Kst[kk * DP + tx * 4];
            float av[4] = {a.x, a.y, a.z, a.w};
            float bv[4] = {bb.x, bb.y, bb.z, bb.w};
            #pragma unroll
            for (int i = 0; i < 4; i++)
                #pragma unroll
                for (int j = 0; j < 4; j++) acc[i][j] += av[i] * bv[j];
        }

        #pragma unroll
        for (int i = 0; i < 4; i++) {
            int t = ty * 4 + i;
            int tq = t0 + t;
            #pragma unroll
            for (int j = 0; j < 4; j++) {
                int jl = tx * 4 + j;
                int jg = j0 + jl;
                int u = tq - jg + WIN;
                float val = -1e30f;
                if (jg >= 0 && jg < SEQ && u >= 0 && u < NREL)
                    val = (acc[i][j] + relb[(size_t)t * NRELP + u]) * 0.03125f;
                Ssm[t * SP + c * 64 + jl] = val;
            }
        }
    }
    __syncthreads();

    // ---- softmax per row (8 warps x 8 rows) ----
    {
        int w = tid >> 5, lane = tid & 31;
        for (int t = w * 8; t < w * 8 + 8; t++) {
            float* row = Ssm + t * SP;
            float m = -1e30f;
            for (int idx = lane; idx < SPAN; idx += 32) m = fmaxf(m, row[idx]);
            #pragma unroll
            for (int o = 16; o > 0; o >>= 1) m = fmaxf(m, __shfl_xor_sync(0xffffffffu, m, o));
            float s = 0.0f;
            for (int idx = lane; idx < SPAN; idx += 32) {
                float e = __expf(row[idx] - m);
                row[idx] = e;
                s += e;
            }
            #pragma unroll
            for (int o = 16; o > 0; o >>= 1) s += __shfl_xor_sync(0xffffffffu, s, o);
            float inv = 1.0f / s;
            for (int idx = lane; idx < SPAN; idx += 32) row[idx] *= inv;
        }
    }

    // ---- O = P @ V ----
    float acco[4][4];
    #pragma unroll
    for (int i = 0; i < 4; i++)
        #pragma unroll
        for (int j = 0; j < 4; j++) acco[i][j] = 0.0f;

    float* Vs = Kst;   // reuse
    for (int c = 0; c < 5; c++) {
        int j0 = t0 - WIN + c * 64;
        __syncthreads();   // Ssm reads from softmax done; Vs free
        #pragma unroll
        for (int l = 0; l < 4; l++) {
            int fidx = tid + l * 256;
            int jl = fidx >> 4;
            int d = (fidx & 15) << 2;
            int jg = j0 + jl;
            float4 v = make_float4(0.f, 0.f, 0.f, 0.f);
            if (jg >= 0 && jg < SEQ) v = *(const float4*)(vb + (size_t)jg * HDIM + d);
            *(float4*)&Vs[jl * DP + d] = v;
        }
        __syncthreads();

        #pragma unroll 8
        for (int jk = 0; jk < 64; jk++) {
            float a0 = Ssm[(ty * 4 + 0) * SP + c * 64 + jk];
            float a1 = Ssm[(ty * 4 + 1) * SP + c * 64 + jk];
            float a2 = Ssm[(ty * 4 + 2) * SP + c * 64 + jk];
            float a3 = Ssm[(ty * 4 + 3) * SP + c * 64 + jk];
            float4 bb = *(float4*)&Vs[jk * DP + tx * 4];
            float bv[4] = {bb.x, bb.y, bb.z, bb.w};
            float av[4] = {a0, a1, a2, a3};
            #pragma unroll
            for (int i = 0; i < 4; i++)
                #pragma unroll
                for (int j = 0; j < 4; j++) acco[i][j] += av[i] * bv[j];
        }
    }

    // write AO[b][tq][h*64+d]
    #pragma unroll
    for (int i = 0; i < 4; i++) {
        int tq = t0 + ty * 4 + i;
        float4 o = make_float4(acco[i][0], acco[i][1], acco[i][2], acco[i][3]);
        *(float4*)&AO[((size_t)(b * SEQ + tq)) * HID + h * HDIM + tx * 4] = o;
    }
}

// ---------------- host ----------------
extern "C" void kernel_launch(void* const* d_in, const int* in_sizes, int n_in,
                              void* d_out, int out_size) {
    const float* x    = (const float*)d_in[0];
    const float* Wq   = (const float*)d_in[1];
    const float* Wk   = (const float*)d_in[2];
    const float* Wv   = (const float*)d_in[3];
    const float* cb   = (const float*)d_in[4];
    const float* rb   = (const float*)d_in[5];
    const float* Wrel = (const float*)d_in[6];
    const float* brel = (const float*)d_in[7];
    const float* Wo   = (const float*)d_in[8];
    const float* bo   = (const float*)d_in[9];
    float* out = (float*)d_out;

    float *qc, *qr, *kt, *vt, *rel, *ao, *rwint;
    cudaGetSymbolAddress((void**)&qc,    g_qc);
    cudaGetSymbolAddress((void**)&qr,    g_qr);
    cudaGetSymbolAddress((void**)&kt,    g_k);
    cudaGetSymbolAddress((void**)&vt,    g_v);
    cudaGetSymbolAddress((void**)&rel,   g_rel);
    cudaGetSymbolAddress((void**)&ao,    g_ao);
    cudaGetSymbolAddress((void**)&rwint, g_rwint);

    // Rwin^T (64 x 384)
    rwin_kernel<<<(64 * NRELP + 255) / 256, 256>>>(Wrel, brel, rwint);

    // QKV projections (M=4096, N=1024, K=1024)
    sgemm_kernel<<<dim3(8, 32), 256>>>(x, EMB, Wq, HID, qc, qr, cb, rb,
                                       BATCH * SEQ, HID, EMB, 3);
    sgemm_kernel<<<dim3(8, 32), 256>>>(x, EMB, Wk, HID, kt, nullptr, nullptr, nullptr,
                                       BATCH * SEQ, HID, EMB, 2);
    sgemm_kernel<<<dim3(8, 32), 256>>>(x, EMB, Wv, HID, vt, nullptr, nullptr, nullptr,
                                       BATCH * SEQ, HID, EMB, 2);

    // REL = Qr @ Rwin^T  (M=65536, N=384, K=64)
    sgemm_kernel<<<dim3(NRELP / 128, (BATCH * HEADS * SEQ) / 128), 256>>>(
        qr, HDIM, rwint, NRELP, rel, nullptr, nullptr, nullptr,
        BATCH * HEADS * SEQ, NRELP, HDIM, 0);

    // windowed attention
    size_t attn_smem = (size_t)ATTN_SMEM_FLOATS * sizeof(float);
    cudaFuncSetAttribute(attn_kernel, cudaFuncAttributeMaxDynamicSharedMemorySize,
                         (int)attn_smem);
    attn_kernel<<<dim3(SEQ / TQ, HEADS, BATCH), 256, attn_smem>>>(qc, kt, vt, rel, ao);

    // output projection: out = AO @ Wo + bo
    sgemm_kernel<<<dim3(8, 32), 256>>>(ao, HID, Wo, EMB, out, nullptr, bo, nullptr,
                                       BATCH * SEQ, EMB, HID, 1);
}